// round 1
// baseline (speedup 1.0000x reference)
#include <cuda_runtime.h>
#include <math.h>

#define BATCH 2048
#define LEN   4096
#define PAD   19                    // max radius (distance 20 -> r = 19)
#define PL    (LEN + 2*PAD)         // 4134 padded length
#define PLA   4136                  // aligned allocation per array
#define NT    256

#define SMEM_FLOATS (4*PLA + 128 + 32)
#define SMEM_BYTES  (SMEM_FLOATS * 4)

// per-row partials: [sumsq, cos_i, p2p_sq_sum, custom_i]
__device__ float g_rowbuf[BATCH * 4];

// ---------------- block reductions ----------------

__device__ __forceinline__ double blockReduceD(double v, double* sc) {
    #pragma unroll
    for (int o = 16; o; o >>= 1) v += __shfl_down_sync(0xffffffffu, v, o);
    int w = threadIdx.x >> 5, l = threadIdx.x & 31;
    if (l == 0) sc[w] = v;
    __syncthreads();
    double r = 0.0;
    int nw = blockDim.x >> 5;
    if (threadIdx.x < 32) {
        r = (threadIdx.x < nw) ? sc[threadIdx.x] : 0.0;
        #pragma unroll
        for (int o = 16; o; o >>= 1) r += __shfl_down_sync(0xffffffffu, r, o);
    }
    __syncthreads();
    return r;  // valid in thread 0
}

__device__ __forceinline__ int blockReduceI(int v, int* sc) {
    #pragma unroll
    for (int o = 16; o; o >>= 1) v += __shfl_down_sync(0xffffffffu, v, o);
    int w = threadIdx.x >> 5, l = threadIdx.x & 31;
    if (l == 0) sc[w] = v;
    __syncthreads();
    int r = 0;
    int nw = blockDim.x >> 5;
    if (threadIdx.x < 32) {
        r = (threadIdx.x < nw) ? sc[threadIdx.x] : 0;
        #pragma unroll
        for (int o = 16; o; o >>= 1) r += __shfl_down_sync(0xffffffffu, r, o);
    }
    __syncthreads();
    return r;  // valid in thread 0
}

// ---------------- van Herk sliding-max building blocks ----------------
// Block-aligned prefix (P) and suffix (S) max over padded array of length PL.
// Window [i-r, i+r] (width w = 2r+1) => pooled = max(S[i-r], P[i+r]) exactly,
// because i+r - (i-r) = w-1 so the two endpoints land in the same aligned
// block (only when i-r is a block start) or adjacent blocks.
__device__ __forceinline__ void buildMaxScan(const float* __restrict__ arr,
                                             float* __restrict__ S,
                                             float* __restrict__ P, int w) {
    int nb = (PL + w - 1) / w;
    for (int job = threadIdx.x; job < 2 * nb; job += blockDim.x) {
        bool pre = job < nb;
        int b = pre ? job : job - nb;
        int s = b * w;
        int e = min(s + w, PL);
        if (pre) {
            float m = -INFINITY;
            for (int j = s; j < e; ++j) { m = fmaxf(m, arr[j]); P[j] = m; }
        } else {
            float m = -INFINITY;
            for (int j = e - 1; j >= s; --j) { m = fmaxf(m, arr[j]); S[j] = m; }
        }
    }
}

__device__ __forceinline__ int countPeaks(const float* __restrict__ arr,
                                          const float* __restrict__ S,
                                          const float* __restrict__ P, int r) {
    int cnt = 0;
    for (int i = threadIdx.x; i < LEN; i += NT) {
        float v = arr[PAD + i];
        if (i > 0 && i < LEN - 1 && v > arr[PAD + i - 1] && v > arr[PAD + i + 1]) {
            float pooled = fmaxf(S[PAD + i - r], P[PAD + i + r]);
            cnt += (v >= pooled);
        }
    }
    return cnt;
}

// ---------------- main per-row kernel ----------------

__global__ void __launch_bounds__(NT)
loss_kernel(const float* __restrict__ xg, const float* __restrict__ yg) {
    extern __shared__ float sm[];
    float* xs = sm;                 // padded in_signal row
    float* ys = sm + PLA;           // padded ref_signal row
    float* S  = sm + 2 * PLA;       // suffix-max scratch
    float* P  = sm + 3 * PLA;       // prefix-max scratch
    unsigned* maskx = (unsigned*)(sm + 4 * PLA);      // 128 words = 4096 bits
    double*   redd  = (double*)(sm + 4 * PLA + 128);  // 16 doubles scratch
    int*      redi  = (int*)(sm + 4 * PLA + 128);     // reused (phases synced)

    const int tid = threadIdx.x;
    const int row = blockIdx.x;
    const float4* x4 = (const float4*)(xg + (size_t)row * LEN);
    const float4* y4 = (const float4*)(yg + (size_t)row * LEN);

    // -inf pads (matches reduce_window init=-inf 'SAME' padding)
    for (int i = tid; i < PAD; i += NT) {
        xs[i] = -INFINITY;            ys[i] = -INFINITY;
        xs[PAD + LEN + i] = -INFINITY; ys[PAD + LEN + i] = -INFINITY;
    }

    // Phase 1: load row into SMEM + elementwise reductions (fp64 accum)
    double sd = 0.0, dt = 0.0, nx = 0.0, ny = 0.0;
    for (int j = tid; j < LEN / 4; j += NT) {
        float4 a = x4[j], b = y4[j];
        int base = PAD + 4 * j;
        xs[base + 0] = a.x; xs[base + 1] = a.y; xs[base + 2] = a.z; xs[base + 3] = a.w;
        ys[base + 0] = b.x; ys[base + 1] = b.y; ys[base + 2] = b.z; ys[base + 3] = b.w;
        double ax = a.x, ay = a.y, az = a.z, aw = a.w;
        double bx = b.x, by = b.y, bz = b.z, bw = b.w;
        double d0 = ax - bx, d1 = ay - by, d2 = az - bz, d3 = aw - bw;
        sd += d0 * d0 + d1 * d1 + d2 * d2 + d3 * d3;
        dt += ax * bx + ay * by + az * bz + aw * bw;
        nx += ax * ax + ay * ay + az * az + aw * aw;
        ny += bx * bx + by * by + bz * bz + bw * bw;
    }
    __syncthreads();

    sd = blockReduceD(sd, redd);
    dt = blockReduceD(dt, redd);
    nx = blockReduceD(nx, redd);
    ny = blockReduceD(ny, redd);

    // Phase 2: distance-20 peak counts (w = 39, r = 19)
    buildMaxScan(xs, S, P, 39);
    __syncthreads();
    int cx = countPeaks(xs, S, P, 19);
    cx = blockReduceI(cx, redi);

    buildMaxScan(ys, S, P, 39);
    __syncthreads();
    int cy = countPeaks(ys, S, P, 19);
    cy = blockReduceI(cy, redi);

    // Phase 3: distance-10 mask for x (w = 19, r = 9) -> bitmask via ballot
    buildMaxScan(xs, S, P, 19);
    __syncthreads();
    {
        int warp = tid >> 5, lane = tid & 31;
        for (int c = warp; c < LEN / 32; c += NT / 32) {
            int i = c * 32 + lane;
            float v = xs[PAD + i];
            bool pk = false;
            if (i > 0 && i < LEN - 1 && v > xs[PAD + i - 1] && v > xs[PAD + i + 1])
                pk = v >= fmaxf(S[PAD + i - 9], P[PAD + i + 9]);
            unsigned bal = __ballot_sync(0xffffffffu, pk);
            if (lane == 0) maskx[c] = bal;
        }
    }
    __syncthreads();

    // Phase 4: distance-10 mask for y fused with p2p accumulation
    buildMaxScan(ys, S, P, 19);
    __syncthreads();
    double pp = 0.0;
    for (int i = tid; i < LEN; i += NT) {
        float vy = ys[PAD + i];
        bool pkm = false;
        if (i > 0 && i < LEN - 1 && vy > ys[PAD + i - 1] && vy > ys[PAD + i + 1])
            pkm = vy >= fmaxf(S[PAD + i - 9], P[PAD + i + 9]);
        float pky = pkm ? vy : 0.0f;
        float pkx = ((maskx[i >> 5] >> (i & 31)) & 1u) ? xs[PAD + i] : 0.0f;
        float d = pkx - pky;
        pp += (double)d * (double)d;
    }
    pp = blockReduceD(pp, redd);

    if (tid == 0) {
        double mse_i = sd / (double)LEN;
        double p2p_i = pp / (double)LEN;
        double cosv  = dt / (sqrt(nx) * sqrt(ny));
        // ALPHA = 1.0, BETA = 0.5
        double custom = (cx != cy) ? mse_i : 0.5 * p2p_i;
        g_rowbuf[row * 4 + 0] = (float)sd;      // raw sumsq (divide later)
        g_rowbuf[row * 4 + 1] = (float)cosv;
        g_rowbuf[row * 4 + 2] = (float)pp;      // raw p2p sq sum
        g_rowbuf[row * 4 + 3] = (float)custom;  // already weighted, per-row
    }
}

// ---------------- final deterministic reduction ----------------

__global__ void __launch_bounds__(256)
finalize_kernel(float* __restrict__ out) {
    __shared__ double sc[32];
    double s0 = 0, s1 = 0, s2 = 0, s3 = 0;
    for (int r = threadIdx.x; r < BATCH; r += blockDim.x) {
        const float* p = &g_rowbuf[r * 4];
        s0 += (double)p[0];
        s1 += (double)p[1];
        s2 += (double)p[2];
        s3 += (double)p[3];
    }
    s0 = blockReduceD(s0, sc);
    s1 = blockReduceD(s1, sc);
    s2 = blockReduceD(s2, sc);
    s3 = blockReduceD(s3, sc);
    if (threadIdx.x == 0) {
        double mse = s0 / ((double)BATCH * (double)LEN);
        out[0] = (float)(mse + s3);          // total_loss = mse_loss + custom_loss
        out[1] = (float)(s1 / (double)BATCH); // cosine_similarity (batch mean)
        out[2] = (float)(s2 / (double)LEN);   // p2p_loss = sum of per-row means
        out[3] = (float)mse;                  // mse_loss
    }
}

extern "C" void kernel_launch(void* const* d_in, const int* in_sizes, int n_in,
                              void* d_out, int out_size) {
    const float* x = (const float*)d_in[0];   // in_signal  [2048, 4096] f32
    const float* y = (const float*)d_in[1];   // ref_signal [2048, 4096] f32
    float* out = (float*)d_out;               // 4 floats

    cudaFuncSetAttribute(loss_kernel,
                         cudaFuncAttributeMaxDynamicSharedMemorySize, SMEM_BYTES);
    loss_kernel<<<BATCH, NT, SMEM_BYTES>>>(x, y);
    finalize_kernel<<<1, 256>>>(out);
}

// round 2
// speedup vs baseline: 1.4519x; 1.4519x over previous
#include <cuda_runtime.h>
#include <math.h>

#define BATCH 2048
#define LEN   4096
#define NT    512
#define W     19              // van Herk block width == window width (distance 10 -> w=19)
#define NB    218             // ceil blocks; 218*19 = 4142
#define ALEN  4142            // scanned length (exact multiple of W)
#define APAD  4144            // allocated floats per array (16B aligned)
#define DOFF  20              // data offset (pad [0,20) = -inf; 20 floats = 80B, 16B aligned)
// tail pad [DOFF+LEN, ALEN) = [4116, 4142) = -inf

// smem layout (bytes): 4 float arrays + mask + reduce scratch
#define SM_FLOATS (4 * APAD)
#define SM_MASK_OFF   (SM_FLOATS * 4)          // 128 unsigned
#define SM_REDD_OFF   (SM_MASK_OFF + 512)      // 16 warps * 5 doubles
#define SM_REDI_OFF   (SM_REDD_OFF + 16*5*8)   // 16 warps * 2 ints
#define SMEM_BYTES    (SM_REDI_OFF + 16*2*4 + 16)

__device__ float4  g_rowbuf[BATCH];   // per-row: {sumsq, cos, p2p_sq_sum, custom}
__device__ unsigned g_count;          // last-block detector (self-resetting)

// ---------------- warp reductions ----------------
__device__ __forceinline__ double wredD(double v) {
    #pragma unroll
    for (int o = 16; o; o >>= 1) v += __shfl_down_sync(0xffffffffu, v, o);
    return v;
}
__device__ __forceinline__ int wredI(int v) {
    #pragma unroll
    for (int o = 16; o; o >>= 1) v += __shfl_down_sync(0xffffffffu, v, o);
    return v;
}

// ---------------- fused van Herk scan ----------------
// One thread per 19-wide block: cache 19 values in registers, emit prefix-max
// into P and suffix-max into S. Lanes stride 19 floats -> bank-conflict-free.
__device__ __forceinline__ void scan19(const float* __restrict__ arr,
                                       float* __restrict__ S,
                                       float* __restrict__ P) {
    for (int b = threadIdx.x; b < NB; b += NT) {
        const int s = b * W;
        float v[W];
        #pragma unroll
        for (int j = 0; j < W; ++j) v[j] = arr[s + j];
        float m = v[0];
        P[s] = m;
        #pragma unroll
        for (int j = 1; j < W; ++j) { m = fmaxf(m, v[j]); P[s + j] = m; }
        m = v[W - 1];
        S[s + W - 1] = m;
        #pragma unroll
        for (int j = W - 2; j >= 0; --j) { m = fmaxf(m, v[j]); S[s + j] = m; }
    }
}

// ---------------- main kernel ----------------
__global__ void __launch_bounds__(NT, 2)
loss_kernel(const float* __restrict__ xg, const float* __restrict__ yg,
            float* __restrict__ out) {
    extern __shared__ char smraw[];
    float*    xs    = (float*)smraw;
    float*    ys    = xs + APAD;
    float*    S     = xs + 2 * APAD;
    float*    P     = xs + 3 * APAD;
    unsigned* maskx = (unsigned*)(smraw + SM_MASK_OFF);
    double*   redd  = (double*)(smraw + SM_REDD_OFF);
    int*      redi  = (int*)(smraw + SM_REDI_OFF);
    __shared__ int s_isLast;

    const int tid  = threadIdx.x;
    const int lane = tid & 31;
    const int wid  = tid >> 5;
    const int row  = blockIdx.x;

    // -inf pads: [0,DOFF) and [DOFF+LEN, ALEN)
    for (int i = tid; i < DOFF + (ALEN - DOFF - LEN); i += NT) {
        int idx = (i < DOFF) ? i : (DOFF + LEN + (i - DOFF));
        xs[idx] = -INFINITY;
        ys[idx] = -INFINITY;
    }

    // Phase 1: vectorized load + fp32 per-thread elementwise partials
    const float4* x4 = (const float4*)(xg + (size_t)row * LEN);
    const float4* y4 = (const float4*)(yg + (size_t)row * LEN);
    float4* xs4 = (float4*)(xs + DOFF);
    float4* ys4 = (float4*)(ys + DOFF);
    float fsd = 0.f, fdt = 0.f, fnx = 0.f, fny = 0.f;
    #pragma unroll
    for (int j = tid; j < LEN / 4; j += NT) {
        float4 a = x4[j], b = y4[j];
        xs4[j] = a; ys4[j] = b;
        float d0 = a.x - b.x, d1 = a.y - b.y, d2 = a.z - b.z, d3 = a.w - b.w;
        fsd += d0*d0 + d1*d1 + d2*d2 + d3*d3;
        fdt += a.x*b.x + a.y*b.y + a.z*b.z + a.w*b.w;
        fnx += a.x*a.x + a.y*a.y + a.z*a.z + a.w*a.w;
        fny += b.x*b.x + b.y*b.y + b.z*b.z + b.w*b.w;
    }
    __syncthreads();                                  // B1

    // Phase 2: scan x, then x-pass (d10 mask bits + sparse d20 count)
    scan19(xs, S, P);
    __syncthreads();                                  // B2

    int cx = 0;
    #pragma unroll
    for (int base = wid * 32; base < LEN; base += NT) {
        const int i = base + lane;
        const float v  = xs[DOFF + i];
        float vl = __shfl_up_sync(0xffffffffu, v, 1);
        float vr = __shfl_down_sync(0xffffffffu, v, 1);
        if (lane == 0)  vl = xs[DOFF + i - 1];
        if (lane == 31) vr = xs[DOFF + i + 1];
        const bool okmax = (i > 0) & (i < LEN - 1) & (v > vl) & (v > vr);
        const bool pk10  = okmax && (v >= fmaxf(S[DOFF + i - 9], P[DOFF + i + 9]));
        const unsigned bal = __ballot_sync(0xffffffffu, pk10);
        if (lane == 0) maskx[base >> 5] = bal;
        if (pk10) {   // d20 peaks are a subset of d10 peaks -> sparse check
            const float lo = fmaxf(S[DOFF + i - 19], P[DOFF + i - 1]);
            const float hi = fmaxf(S[DOFF + i + 1],  P[DOFF + i + 19]);
            cx += (v >= lo) && (v >= hi);
        }
    }
    __syncthreads();                                  // B3 (S,P,mask handoff)

    // Phase 3: scan y, then y-pass (d10 y, sparse d20 count, fused p2p)
    scan19(ys, S, P);
    __syncthreads();                                  // B4

    int cy = 0;
    float fpp = 0.f;
    #pragma unroll
    for (int base = wid * 32; base < LEN; base += NT) {
        const int i = base + lane;
        const float v  = ys[DOFF + i];
        float vl = __shfl_up_sync(0xffffffffu, v, 1);
        float vr = __shfl_down_sync(0xffffffffu, v, 1);
        if (lane == 0)  vl = ys[DOFF + i - 1];
        if (lane == 31) vr = ys[DOFF + i + 1];
        const bool okmax = (i > 0) & (i < LEN - 1) & (v > vl) & (v > vr);
        const bool pk10  = okmax && (v >= fmaxf(S[DOFF + i - 9], P[DOFF + i + 9]));
        if (pk10) {
            const float lo = fmaxf(S[DOFF + i - 19], P[DOFF + i - 1]);
            const float hi = fmaxf(S[DOFF + i + 1],  P[DOFF + i + 19]);
            cy += (v >= lo) && (v >= hi);
        }
        const float pky = pk10 ? v : 0.f;
        const unsigned wm = maskx[base >> 5];
        const float pkx = ((wm >> lane) & 1u) ? xs[DOFF + i] : 0.f;
        const float dd = pkx - pky;
        fpp += dd * dd;
    }

    // Phase 4: single combined block reduction (5 doubles + 2 ints)
    double vals[5] = {(double)fsd, (double)fdt, (double)fnx, (double)fny, (double)fpp};
    #pragma unroll
    for (int k = 0; k < 5; ++k) vals[k] = wredD(vals[k]);
    cx = wredI(cx);
    cy = wredI(cy);
    if (lane == 0) {
        #pragma unroll
        for (int k = 0; k < 5; ++k) redd[wid * 5 + k] = vals[k];
        redi[wid * 2 + 0] = cx;
        redi[wid * 2 + 1] = cy;
    }
    __syncthreads();                                  // B5

    if (tid == 0) {
        double sd = 0, dt = 0, nx = 0, ny = 0, pp = 0;
        int tcx = 0, tcy = 0;
        #pragma unroll
        for (int w = 0; w < NT / 32; ++w) {
            sd += redd[w * 5 + 0]; dt += redd[w * 5 + 1];
            nx += redd[w * 5 + 2]; ny += redd[w * 5 + 3];
            pp += redd[w * 5 + 4];
            tcx += redi[w * 2 + 0]; tcy += redi[w * 2 + 1];
        }
        const double mse_i = sd / (double)LEN;
        const double p2p_i = pp / (double)LEN;
        const double cosv  = dt / (sqrt(nx) * sqrt(ny));
        const double custom = (tcx != tcy) ? mse_i : 0.5 * p2p_i;   // ALPHA=1, BETA=0.5
        float4 r;
        r.x = (float)sd; r.y = (float)cosv; r.z = (float)pp; r.w = (float)custom;
        g_rowbuf[row] = r;
        __threadfence();
        s_isLast = (atomicAdd(&g_count, 1u) == BATCH - 1);
    }
    __syncthreads();                                  // B6

    // Phase 5: last block performs the deterministic final reduction
    if (s_isLast) {
        double s0 = 0, s1 = 0, s2 = 0, s3 = 0;
        for (int r = tid; r < BATCH; r += NT) {
            float4 p = g_rowbuf[r];
            s0 += (double)p.x; s1 += (double)p.y;
            s2 += (double)p.z; s3 += (double)p.w;
        }
        s0 = wredD(s0); s1 = wredD(s1); s2 = wredD(s2); s3 = wredD(s3);
        if (lane == 0) {
            redd[wid * 4 + 0] = s0; redd[wid * 4 + 1] = s1;
            redd[wid * 4 + 2] = s2; redd[wid * 4 + 3] = s3;
        }
        __syncthreads();
        if (tid == 0) {
            double t0 = 0, t1 = 0, t2 = 0, t3 = 0;
            #pragma unroll
            for (int w = 0; w < NT / 32; ++w) {
                t0 += redd[w * 4 + 0]; t1 += redd[w * 4 + 1];
                t2 += redd[w * 4 + 2]; t3 += redd[w * 4 + 3];
            }
            const double mse = t0 / ((double)BATCH * (double)LEN);
            out[0] = (float)(mse + t3);              // total_loss
            out[1] = (float)(t1 / (double)BATCH);    // cosine_similarity
            out[2] = (float)(t2 / (double)LEN);      // p2p_loss
            out[3] = (float)mse;                     // mse_loss
            g_count = 0;                             // self-reset for next replay
        }
    }
}

extern "C" void kernel_launch(void* const* d_in, const int* in_sizes, int n_in,
                              void* d_out, int out_size) {
    const float* x = (const float*)d_in[0];   // in_signal  [2048, 4096] f32
    const float* y = (const float*)d_in[1];   // ref_signal [2048, 4096] f32
    float* out = (float*)d_out;

    cudaFuncSetAttribute(loss_kernel,
                         cudaFuncAttributeMaxDynamicSharedMemorySize, SMEM_BYTES);
    loss_kernel<<<BATCH, NT, SMEM_BYTES>>>(x, y, out);
}

// round 3
// speedup vs baseline: 2.0253x; 1.3949x over previous
#include <cuda_runtime.h>
#include <math.h>

#define BATCH 2048
#define LEN   4096
#define NT    256
#define W     19
#define NBLK  218              // 218*19 = 4142 >= 20+4096+19
#define PRE   32               // front guard (-inf), covers reads down to p=-10
#define ASZ   4208             // PRE + 4142 + tail guard, 16B-aligned
// padded coordinate p: signal i lives at p = 20+i, smem idx = p + PRE = 52+i
#define DIDX  52               // smem index of i=0
#define PMIN  21               // first interior p (i=1)
#define PMAX  4114             // last interior p (i=LEN-2)

__device__ float4   g_rowbuf[BATCH];
__device__ unsigned g_count;

// ---------------- warp reductions ----------------
__device__ __forceinline__ double wredD(double v) {
    #pragma unroll
    for (int o = 16; o; o >>= 1) v += __shfl_down_sync(0xffffffffu, v, o);
    return v;
}
__device__ __forceinline__ int wredI(int v) {
    #pragma unroll
    for (int o = 16; o; o >>= 1) v += __shfl_down_sync(0xffffffffu, v, o);
    return v;
}

// ---------------- register-resident van Herk block ----------------
// Thread owns padded block [s, s+19). Computes d10 peak mask (bit j) and d20
// peak count from its own 39-value neighborhood; optionally fuses the p2p
// accumulation against the x-signal's peak mask (P2P=true for the y pass).
template<bool P2P>
__device__ __forceinline__ void processBlock(const float* __restrict__ A, int s,
                                             unsigned& mask, int& cnt20,
                                             const float* __restrict__ X,
                                             unsigned maskx, float& pp) {
    const float* B = A + PRE + s;    // B[j] = value at p = s+j

    float c[W];
    #pragma unroll
    for (int j = 0; j < W; ++j) c[j] = B[j];

    // left-block suffix maxes: Sl[k] = max(A[p = s-10+k .. s-1]), k=1..9
    float Sl[10];
    Sl[9] = B[-1];
    #pragma unroll
    for (int k = 8; k >= 1; --k) Sl[k] = fmaxf(B[k - 10], Sl[k + 1]);

    // right-block prefix maxes: Pr[k] = max(B[19 .. 19+k]), k=0..8
    float Pr[9];
    Pr[0] = B[W];
    #pragma unroll
    for (int k = 1; k < 9; ++k) Pr[k] = fmaxf(Pr[k - 1], B[W + k]);

    // own prefix: Pown[t] = max(c[0..t]); own suffix: Sown[t] = max(c[t..18])
    float Pown[W], Sown[W];
    Pown[0] = c[0];
    #pragma unroll
    for (int t = 1; t < W; ++t) Pown[t] = fmaxf(Pown[t - 1], c[t]);
    Sown[W - 1] = c[W - 1];
    #pragma unroll
    for (int t = W - 2; t >= 0; --t) Sown[t] = fmaxf(c[t], Sown[t + 1]);

    mask = 0u; cnt20 = 0;
    #pragma unroll
    for (int j = 0; j < W; ++j) {
        const int p = s + j;
        const float v = c[j];
        // pooled19 = max over [p-9, p+9]; endpoints land in own block or halo
        const float Sp = (j >= 9) ? Sown[j - 9] : Sl[j + 1];
        const float Pp = (j <= 9) ? Pown[j + 9] : Pr[j - 10];
        const float left  = (j == 0)     ? Sl[9] : c[j - 1];
        const float right = (j == W - 1) ? Pr[0] : c[j + 1];
        const bool ok = (p >= PMIN) & (p <= PMAX) & (v > left) & (v > right);
        const bool pk = ok && (v >= fmaxf(Sp, Pp));
        float pky = 0.f;
        if (pk) {
            mask |= (1u << j);
            pky = v;
            // d20: also require v >= max over [p-19,p-10] and [p+10,p+19]
            float lo = B[j - 19], hi = B[j + 10];
            #pragma unroll
            for (int t = 1; t < 10; ++t) {
                lo = fmaxf(lo, B[j - 19 + t]);
                hi = fmaxf(hi, B[j + 10 + t]);
            }
            cnt20 += (v >= lo) && (v >= hi);
        }
        if (P2P) {
            const float pkx = ((maskx >> j) & 1u) ? X[PRE + s + j] : 0.f;
            const float d = pkx - pky;
            pp += d * d;
        }
    }
}

// ---------------- main kernel ----------------
__global__ void __launch_bounds__(NT, 3)
loss_kernel(const float* __restrict__ xg, const float* __restrict__ yg,
            float* __restrict__ out) {
    __shared__ float  xs[ASZ];
    __shared__ float  ys[ASZ];
    __shared__ double redd[8 * 5];
    __shared__ int    redi[8 * 2];
    __shared__ int    s_isLast;

    const int tid  = threadIdx.x;
    const int lane = tid & 31;
    const int wid  = tid >> 5;
    const int row  = blockIdx.x;

    // -inf guards: idx [0,52) and [4148, 4208)
    {
        int i = tid;                           // 112 slots, NT=256: one shot
        if (i < 52 + (ASZ - 4148)) {
            int idx = (i < 52) ? i : 4148 + (i - 52);
            xs[idx] = -INFINITY;
            ys[idx] = -INFINITY;
        }
    }

    // Phase 1: coalesced load + fp32 elementwise partials
    const float4* x4 = (const float4*)(xg + (size_t)row * LEN);
    const float4* y4 = (const float4*)(yg + (size_t)row * LEN);
    float4* xs4 = (float4*)(xs + DIDX);
    float4* ys4 = (float4*)(ys + DIDX);
    float fsd = 0.f, fdt = 0.f, fnx = 0.f, fny = 0.f;
    #pragma unroll
    for (int j = tid; j < LEN / 4; j += NT) {
        float4 a = x4[j], b = y4[j];
        xs4[j] = a; ys4[j] = b;
        float d0 = a.x - b.x, d1 = a.y - b.y, d2 = a.z - b.z, d3 = a.w - b.w;
        fsd += d0*d0 + d1*d1 + d2*d2 + d3*d3;
        fdt += a.x*b.x + a.y*b.y + a.z*b.z + a.w*b.w;
        fnx += a.x*a.x + a.y*a.y + a.z*a.z + a.w*a.w;
        fny += b.x*b.x + b.y*b.y + b.z*b.z + b.w*b.w;
    }
    __syncthreads();                                   // B1: row resident

    // Phase 2: per-thread block processing, x then y (registers only)
    int cx = 0, cy = 0;
    float fpp = 0.f;
    if (tid < NBLK) {
        const int s = tid * W;
        unsigned mx, my;
        int c20;
        processBlock<false>(xs, s, mx, c20, ys, 0u, fpp);
        cx = c20;
        processBlock<true>(ys, s, my, c20, xs, mx, fpp);
        cy = c20;
    }

    // Phase 3: combined block reduction (5 doubles + 2 ints)
    double vals[5] = {(double)fsd, (double)fdt, (double)fnx, (double)fny, (double)fpp};
    #pragma unroll
    for (int k = 0; k < 5; ++k) vals[k] = wredD(vals[k]);
    cx = wredI(cx);
    cy = wredI(cy);
    if (lane == 0) {
        #pragma unroll
        for (int k = 0; k < 5; ++k) redd[wid * 5 + k] = vals[k];
        redi[wid * 2 + 0] = cx;
        redi[wid * 2 + 1] = cy;
    }
    __syncthreads();                                   // B2

    if (tid == 0) {
        double sd = 0, dt = 0, nx = 0, ny = 0, pp = 0;
        int tcx = 0, tcy = 0;
        #pragma unroll
        for (int w = 0; w < NT / 32; ++w) {
            sd += redd[w * 5 + 0]; dt += redd[w * 5 + 1];
            nx += redd[w * 5 + 2]; ny += redd[w * 5 + 3];
            pp += redd[w * 5 + 4];
            tcx += redi[w * 2 + 0]; tcy += redi[w * 2 + 1];
        }
        const double mse_i = sd / (double)LEN;
        const double p2p_i = pp / (double)LEN;
        const double cosv  = dt / (sqrt(nx) * sqrt(ny));
        const double custom = (tcx != tcy) ? mse_i : 0.5 * p2p_i;  // ALPHA=1, BETA=0.5
        float4 r;
        r.x = (float)sd; r.y = (float)cosv; r.z = (float)pp; r.w = (float)custom;
        g_rowbuf[row] = r;
        __threadfence();
        s_isLast = (atomicAdd(&g_count, 1u) == BATCH - 1);
    }
    __syncthreads();                                   // B3

    // Phase 4: last block does the deterministic final reduction
    if (s_isLast) {
        double s0 = 0, s1 = 0, s2 = 0, s3 = 0;
        for (int r = tid; r < BATCH; r += NT) {
            float4 p = g_rowbuf[r];
            s0 += (double)p.x; s1 += (double)p.y;
            s2 += (double)p.z; s3 += (double)p.w;
        }
        s0 = wredD(s0); s1 = wredD(s1); s2 = wredD(s2); s3 = wredD(s3);
        if (lane == 0) {
            redd[wid * 4 + 0] = s0; redd[wid * 4 + 1] = s1;
            redd[wid * 4 + 2] = s2; redd[wid * 4 + 3] = s3;
        }
        __syncthreads();
        if (tid == 0) {
            double t0 = 0, t1 = 0, t2 = 0, t3 = 0;
            #pragma unroll
            for (int w = 0; w < NT / 32; ++w) {
                t0 += redd[w * 4 + 0]; t1 += redd[w * 4 + 1];
                t2 += redd[w * 4 + 2]; t3 += redd[w * 4 + 3];
            }
            const double mse = t0 / ((double)BATCH * (double)LEN);
            out[0] = (float)(mse + t3);               // total_loss
            out[1] = (float)(t1 / (double)BATCH);     // cosine_similarity
            out[2] = (float)(t2 / (double)LEN);       // p2p_loss
            out[3] = (float)mse;                      // mse_loss
            g_count = 0;                              // reset for next replay
        }
    }
}

extern "C" void kernel_launch(void* const* d_in, const int* in_sizes, int n_in,
                              void* d_out, int out_size) {
    const float* x = (const float*)d_in[0];   // in_signal  [2048, 4096] f32
    const float* y = (const float*)d_in[1];   // ref_signal [2048, 4096] f32
    float* out = (float*)d_out;
    loss_kernel<<<BATCH, NT>>>(x, y, out);
}